// round 6
// baseline (speedup 1.0000x reference)
#include <cuda_runtime.h>
#include <cuda_bf16.h>

// out shape: (B=8, C=256, H=128, W=128) fp32, row-major. Output is independent
// of the input tensor and identical across batches:
//   out[b,c,i,j] = c<128 ? trig_c(i) : trig_{c-128}(j)
//   trig_cc(p)   = (cc even ? sin : cos)(p * 10000^(-floor(cc/2)/128))
//
// Write-injection at the SM->LTS fabric cap (~6.9 TB/s). R3<->R4 established:
// deeper per-thread .cs store bursts at lower CTA concurrency win. This round
// exploits batch invariance at the BLOCK level: each block owns channel c for
// batches b and b+4 (identical plane data), stages 16 float4 once, and bursts
// 32 back-to-back streaming STG.128 (16 per batch copy). Half the CTAs,
// double the per-thread store stream, same register staging cost.

__global__ __launch_bounds__(256) void pe2d_kernel(float* __restrict__ out) {
    const int blk = blockIdx.x;       // 0..1023 = b(0..3)*256 + c
    const int c   = blk & 255;
    const int tid = threadIdx.x;

    __shared__ float s[128];

    if (tid < 128) {
        const int cc    = c & 127;        // channel within half
        const int pairk = cc >> 1;        // floor(cc/2)
        const float LOG2_10000 = 13.28771237954945f;
        float inv_dim = exp2f(-(float)pairk * (LOG2_10000 / 128.0f));
        float arg = (float)tid * inv_dim; // tid = position (i or j)
        float sv, cv;
        sincosf(arg, &sv, &cv);
        s[tid] = (cc & 1) ? cv : sv;
    }
    __syncthreads();

    // Stage the plane's 16 float4 per thread once (consecutive lanes ->
    // consecutive float4; 512B/warp per store, fully coalesced).
    float4 v[16];
    if (c < 128) {
        // value constant along j: row index = idx4 >> 5 (warp-uniform)
        #pragma unroll
        for (int t = 0; t < 16; t++) {
            const float x = s[(tid + t * 256) >> 5];   // smem broadcast
            v[t] = make_float4(x, x, x, x);
        }
    } else {
        // value varies along j only: every row replicates s[0..127]
        const float4* s4 = reinterpret_cast<const float4*>(s);
        #pragma unroll
        for (int t = 0; t < 16; t++) {
            v[t] = s4[(tid + t * 256) & 31];           // conflict-free LDS.128
        }
    }

    // Two identical batch copies: plane ids blk and blk+1024
    // (batch b and b+4, same channel). 32 streaming stores back-to-back.
    float4* o1 = reinterpret_cast<float4*>(out) + (size_t)blk * 4096 + tid;
    float4* o2 = o1 + (size_t)1024 * 4096;
    #pragma unroll
    for (int t = 0; t < 16; t++) {
        __stcs(o1 + t * 256, v[t]);                    // st.global.cs.v4
    }
    #pragma unroll
    for (int t = 0; t < 16; t++) {
        __stcs(o2 + t * 256, v[t]);
    }
}

extern "C" void kernel_launch(void* const* d_in, const int* in_sizes, int n_in,
                              void* d_out, int out_size) {
    (void)d_in; (void)in_sizes; (void)n_in; (void)out_size;
    // 4 batches * 256 channels; each block also writes batch b+4's copy
    pe2d_kernel<<<1024, 256>>>((float*)d_out);
}

// round 7
// speedup vs baseline: 1.0731x; 1.0731x over previous
#include <cuda_runtime.h>
#include <cuda_bf16.h>

// out shape: (B=8, C=256, H=128, W=128) fp32, row-major. Output is independent
// of the input tensor and identical across batches:
//   out[b,c,i,j] = c<128 ? trig_c(i) : trig_{c-128}(j)
//   trig_cc(p)   = (cc even ? sin : cos)(p * 10000^(-floor(cc/2)/128))
//
// FINAL (converged, reproduced twice at 23.008us e2e / ~19.6-20.1us kernel):
// pure write-injection at the SM->LTS fabric write cap (~6300 B/cyc, 6.86 TB/s
// achieved = 99.4%). One block per (b,c) plane; 128 unique values computed in
// smem (sincosf once per thread); 16 float4 staged in registers, then burst as
// 16 back-to-back streaming STG.128 (.cs, evict-first).
//
// Design-space results from this session:
//   R2  TMA bulk stores:           23.4us kernel (-10%) — same LTS cap, worse issue
//   R4  8-deep bursts, occ 81%:    23.3us kernel (-19%) — stores need burst depth,
//                                  not latency hiding; low occ is fine
//   R6  32-deep bursts, 1024 CTAs: 20.3us kernel (neutral), e2e +8% (wave tail)
//   R3/R5 (this config):           best, at the fabric floor (19.4us model).

__global__ __launch_bounds__(256) void pe2d_kernel(float* __restrict__ out) {
    const int bc  = blockIdx.x;       // b*256 + c
    const int c   = bc & 255;
    const int tid = threadIdx.x;

    __shared__ float s[128];

    if (tid < 128) {
        const int cc    = c & 127;        // channel within half
        const int pairk = cc >> 1;        // floor(cc/2)
        const float LOG2_10000 = 13.28771237954945f;
        float inv_dim = exp2f(-(float)pairk * (LOG2_10000 / 128.0f));
        float arg = (float)tid * inv_dim; // tid = position (i or j)
        float sv, cv;
        sincosf(arg, &sv, &cv);
        s[tid] = (cc & 1) ? cv : sv;
    }
    __syncthreads();

    // Per-thread: 16 float4 stores, consecutive lanes -> consecutive float4
    // (512B per warp per store, fully coalesced). Stage all values in
    // registers FIRST, then burst the 16 streaming stores back-to-back so the
    // LSU/L2 write queue stays saturated with no interleaved LDS/index math.
    float4 v[16];
    if (c < 128) {
        // value constant along j: row index = idx4 >> 5
        #pragma unroll
        for (int t = 0; t < 16; t++) {
            const int row = (tid + t * 256) >> 5;   // warp-uniform
            const float x = s[row];                 // smem broadcast
            v[t] = make_float4(x, x, x, x);
        }
    } else {
        // value varies along j only: every row replicates s[0..127]
        const float4* s4 = reinterpret_cast<const float4*>(s);
        #pragma unroll
        for (int t = 0; t < 16; t++) {
            v[t] = s4[(tid + t * 256) & 31];        // conflict-free LDS.128
        }
    }

    float4* outp = reinterpret_cast<float4*>(out) + (size_t)bc * 4096 + tid;
    #pragma unroll
    for (int t = 0; t < 16; t++) {
        __stcs(outp + t * 256, v[t]);               // st.global.cs.v4 (evict-first)
    }
}

extern "C" void kernel_launch(void* const* d_in, const int* in_sizes, int n_in,
                              void* d_out, int out_size) {
    (void)d_in; (void)in_sizes; (void)n_in; (void)out_size;
    // 8 batches * 256 channels = 2048 planes
    pe2d_kernel<<<2048, 256>>>((float*)d_out);
}